// round 1
// baseline (speedup 1.0000x reference)
#include <cuda_runtime.h>
#include <cstdint>
#include <cstddef>

#define B_ 32
#define T_ 2048
#define D_ 512
#define U_ 512
#define CTX_OFF (B_*D_)   // 16384 floats: context region; attn follows

// ---------------- scratch (no allocations allowed) ----------------
__device__ float g_qproj[B_*U_];        // q @ W1 + b1 (+ nothing else)
__device__ float g_pscore[4*B_*T_];     // per-uTile partial scores

// ---------------- small helpers ----------------
__device__ __forceinline__ uint32_t f2tf32(float f){
    uint32_t r; asm("cvt.rna.tf32.f32 %0, %1;" : "=r"(r) : "f"(f)); return r;
}
__device__ __forceinline__ float tanh_fast(float x){
    float r; asm("tanh.approx.f32 %0, %1;" : "=f"(r) : "f"(x)); return r;
}
__device__ __forceinline__ void cp16(uint32_t smem, const void* gmem){
    asm volatile("cp.async.cg.shared.global [%0], [%1], 16;\n" :: "r"(smem), "l"(gmem));
}
__device__ __forceinline__ void mma_tf32(float c[4], const uint32_t a[4], const uint32_t b[2]){
    asm volatile(
        "mma.sync.aligned.m16n8k8.row.col.f32.tf32.tf32.f32 "
        "{%0,%1,%2,%3}, {%4,%5,%6,%7}, {%8,%9}, {%0,%1,%2,%3};\n"
        : "+f"(c[0]), "+f"(c[1]), "+f"(c[2]), "+f"(c[3])
        : "r"(a[0]), "r"(a[1]), "r"(a[2]), "r"(a[3]),
          "r"(b[0]), "r"(b[1]));
}

// ---------------- kernel 1: q_proj = query @ W1 + b1 ; zero context region ----------------
__global__ __launch_bounds__(512) void qproj_kernel(
    const float* __restrict__ query, const float* __restrict__ W1,
    const float* __restrict__ W1b, float* __restrict__ out)
{
    const int b = blockIdx.x, tid = threadIdx.x;
    __shared__ float sq[D_];
    sq[tid] = query[b*D_ + tid];
    __syncthreads();
    float acc = W1b[tid];
    #pragma unroll 8
    for (int d = 0; d < D_; d++)
        acc += sq[d] * W1[(size_t)d*U_ + tid];
    g_qproj[b*U_ + tid] = acc;
    out[b*D_ + tid] = 0.0f;   // zero context (d_out is poisoned)
}

// ---------------- kernel 2: fused score GEMM ----------------
// score_partial[uTile][b][t] = sum_{u in uTile} Vw[u] * tanh(qproj[b,u] + W2b[u] + sum_d values[b,t,d]*W2[d,u])
// Block: 256 threads (8 warps as 2x4), tile M=64 (t) x N=128 (u), K streamed in 16-chunks.
#define BM 64
#define BN 128
#define BK 16
#define NKC (D_/BK)     // 32
#define ALD 20          // As row stride (pad: conflict-free fragment loads)
#define BLD 136         // Bs row stride (pad: conflict-free fragment loads)

__global__ __launch_bounds__(256) void score_kernel(
    const float* __restrict__ values, const float* __restrict__ W2,
    const float* __restrict__ W2b,    const float* __restrict__ Vw)
{
    __shared__ float As[2][BM][ALD];     // [t][k]
    __shared__ float Bs[2][BK][BLD];     // [k][u]
    __shared__ float sQP[BN];            // qproj + W2b slice
    __shared__ float sVw[BN];
    __shared__ float ssum[4][BM];

    const int tid = threadIdx.x;
    const int b  = blockIdx.z;
    const int t0 = blockIdx.y * BM;
    const int u0 = blockIdx.x * BN;
    const int warp = tid >> 5, lane = tid & 31;
    const int g = lane >> 2, tg = lane & 3;
    const int wm = warp >> 2, wn = warp & 3;   // 2 x 4 warps
    const int m0 = wm * 32,  n0 = wn * 32;

    if (tid < BN) sQP[tid] = g_qproj[b*U_ + u0 + tid] + W2b[u0 + tid];
    else          sVw[tid - BN] = Vw[u0 + tid - BN];

    const float* gA = values + ((size_t)b*T_ + t0) * D_;

    // async-load of one K-chunk
    const int at = tid >> 2, ac = tid & 3;        // A: 64 rows x 4 chunks of 16B
    float c[2][4][4];
    #pragma unroll
    for (int mi = 0; mi < 2; mi++)
        #pragma unroll
        for (int ni = 0; ni < 4; ni++)
            #pragma unroll
            for (int q = 0; q < 4; q++) c[mi][ni][q] = 0.0f;

    #define LOAD_CHUNK(KC, BUF) do {                                            \
        cp16((uint32_t)__cvta_generic_to_shared(&As[BUF][at][ac*4]),            \
             gA + (size_t)at*D_ + (KC)*BK + ac*4);                              \
        _Pragma("unroll")                                                       \
        for (int j = 0; j < 2; j++) {                                           \
            int idx = tid + j*256, kr = idx >> 5, cc = idx & 31;                \
            cp16((uint32_t)__cvta_generic_to_shared(&Bs[BUF][kr][cc*4]),        \
                 W2 + (size_t)((KC)*BK + kr)*U_ + u0 + cc*4);                   \
        }                                                                       \
    } while (0)

    LOAD_CHUNK(0, 0);
    asm volatile("cp.async.commit_group;\n");
    LOAD_CHUNK(1, 1);
    asm volatile("cp.async.commit_group;\n");

    for (int kc = 0; kc < NKC; kc++) {
        if (kc < NKC-2) asm volatile("cp.async.wait_group 1;\n");
        else            asm volatile("cp.async.wait_group 0;\n");
        __syncthreads();
        const int buf = kc & 1;

        #pragma unroll
        for (int ks = 0; ks < BK; ks += 8) {
            uint32_t a[2][4], bb[4][2];
            #pragma unroll
            for (int mi = 0; mi < 2; mi++) {
                int r = m0 + mi*16 + g;
                a[mi][0] = f2tf32(As[buf][r    ][ks + tg    ]);
                a[mi][1] = f2tf32(As[buf][r + 8][ks + tg    ]);
                a[mi][2] = f2tf32(As[buf][r    ][ks + tg + 4]);
                a[mi][3] = f2tf32(As[buf][r + 8][ks + tg + 4]);
            }
            #pragma unroll
            for (int ni = 0; ni < 4; ni++) {
                int cN = n0 + ni*8 + g;
                bb[ni][0] = f2tf32(Bs[buf][ks + tg    ][cN]);
                bb[ni][1] = f2tf32(Bs[buf][ks + tg + 4][cN]);
            }
            #pragma unroll
            for (int mi = 0; mi < 2; mi++)
                #pragma unroll
                for (int ni = 0; ni < 4; ni++)
                    mma_tf32(c[mi][ni], a[mi], bb[ni]);
        }
        __syncthreads();
        if (kc + 2 < NKC) {
            LOAD_CHUNK(kc + 2, buf);
            asm volatile("cp.async.commit_group;\n");
        }
    }
    #undef LOAD_CHUNK

    // ---- epilogue: tanh + dot with Vw, reduce over u ----
    float rs[2][2] = {{0.f,0.f},{0.f,0.f}};   // [mi][row-half]
    #pragma unroll
    for (int mi = 0; mi < 2; mi++)
        #pragma unroll
        for (int ni = 0; ni < 4; ni++) {
            int cN0 = n0 + ni*8 + 2*tg;
            #pragma unroll
            for (int h = 0; h < 2; h++)
                #pragma unroll
                for (int q = 0; q < 2; q++) {
                    int col = cN0 + q;
                    float v = c[mi][ni][h*2 + q] + sQP[col];
                    rs[mi][h] += tanh_fast(v) * sVw[col];
                }
        }
    #pragma unroll
    for (int mi = 0; mi < 2; mi++)
        #pragma unroll
        for (int h = 0; h < 2; h++) {
            rs[mi][h] += __shfl_xor_sync(0xffffffffu, rs[mi][h], 1);
            rs[mi][h] += __shfl_xor_sync(0xffffffffu, rs[mi][h], 2);
        }
    if (tg == 0) {
        #pragma unroll
        for (int mi = 0; mi < 2; mi++)
            #pragma unroll
            for (int h = 0; h < 2; h++)
                ssum[wn][m0 + mi*16 + h*8 + g] = rs[mi][h];
    }
    __syncthreads();
    if (tid < BM) {
        float s = ssum[0][tid] + ssum[1][tid] + ssum[2][tid] + ssum[3][tid];
        g_pscore[(size_t)blockIdx.x*(B_*T_) + b*T_ + t0 + tid] = s;
    }
}

// ---------------- kernel 3: softmax over T, write attn to d_out ----------------
__global__ __launch_bounds__(256) void softmax_kernel(
    const float* __restrict__ Vb, float* __restrict__ out)
{
    const int b = blockIdx.x, tid = threadIdx.x;
    __shared__ float red[256];
    float loc[8];
    const float vb = Vb[0];
    float mx = -1e30f;
    #pragma unroll
    for (int j = 0; j < 8; j++) {
        int t = tid + j*256;
        float s = g_pscore[0*B_*T_ + b*T_ + t] + g_pscore[1*B_*T_ + b*T_ + t]
                + g_pscore[2*B_*T_ + b*T_ + t] + g_pscore[3*B_*T_ + b*T_ + t] + vb;
        loc[j] = s;
        mx = fmaxf(mx, s);
    }
    red[tid] = mx; __syncthreads();
    #pragma unroll
    for (int s = 128; s > 0; s >>= 1) {
        if (tid < s) red[tid] = fmaxf(red[tid], red[tid + s]);
        __syncthreads();
    }
    mx = red[0]; __syncthreads();
    float se = 0.f;
    #pragma unroll
    for (int j = 0; j < 8; j++) { loc[j] = __expf(loc[j] - mx); se += loc[j]; }
    red[tid] = se; __syncthreads();
    #pragma unroll
    for (int s = 128; s > 0; s >>= 1) {
        if (tid < s) red[tid] += red[tid + s];
        __syncthreads();
    }
    const float inv = 1.0f / red[0];
    #pragma unroll
    for (int j = 0; j < 8; j++)
        out[CTX_OFF + b*T_ + tid + j*256] = loc[j] * inv;
}

// ---------------- kernel 4: context = sum_t attn * values ----------------
__global__ __launch_bounds__(512) void context_kernel(
    const float* __restrict__ values, float* __restrict__ out)
{
    const int b = blockIdx.x, sp = blockIdx.y, tid = threadIdx.x;
    __shared__ float sa[256];
    const int t0 = sp * 256;
    if (tid < 256) sa[tid] = out[CTX_OFF + b*T_ + t0 + tid];
    __syncthreads();
    const float* vp = values + ((size_t)b*T_ + t0)*D_ + tid;
    float acc = 0.f;
    #pragma unroll 4
    for (int tt = 0; tt < 256; tt++)
        acc += sa[tt] * vp[(size_t)tt * D_];
    atomicAdd(&out[b*D_ + tid], acc);
}

// ---------------- launch ----------------
extern "C" void kernel_launch(void* const* d_in, const int* in_sizes, int n_in,
                              void* d_out, int out_size)
{
    const float* query  = (const float*)d_in[0];
    const float* values = (const float*)d_in[1];
    const float* W1w    = (const float*)d_in[2];
    const float* W1b    = (const float*)d_in[3];
    const float* W2w    = (const float*)d_in[4];
    const float* W2b    = (const float*)d_in[5];
    const float* Vw     = (const float*)d_in[6];
    const float* Vb     = (const float*)d_in[7];
    float* out = (float*)d_out;

    qproj_kernel<<<B_, 512>>>(query, W1w, W1b, out);
    dim3 g2(U_/BN, T_/BM, B_);           // uTile fastest => L2 reuse of values tiles
    score_kernel<<<g2, 256>>>(values, W2w, W2b, Vw);
    softmax_kernel<<<B_, 256>>>(Vb, out);
    context_kernel<<<dim3(B_, 8), 512>>>(values, out);
}

// round 5
// speedup vs baseline: 1.2437x; 1.2437x over previous
#include <cuda_runtime.h>
#include <cstdint>
#include <cstddef>

#define B_ 32
#define T_ 2048
#define D_ 512
#define U_ 512
#define CTX_OFF (B_*D_)   // context at [0:16384], attn at [16384:]

// score-GEMM tiling (mma.sync tf32 path; tcgen05 PTX is rejected at compute_103)
#define BM 128
#define BN 128
#define BK 32
#define NKC (D_/BK)       // 16 chunks
#define N_UT (U_/BN)      // 4 u-tiles
#define LD 36             // padded row stride (floats) — conflict-free frags

// dynamic smem for score kernel
#define SM_QP    0                      // 128 floats
#define SM_VW    512                    // 128 floats
#define SM_RED   1024                   // ssum[2][128] floats
#define SM_A0    2048
#define SM_TILE  (BM*LD*4)              // 18432 B
#define SM_STAGE (2*SM_TILE)            // A + B = 36864 B
#define SM_TOTAL (SM_A0 + 2*SM_STAGE)   // 75776 B

// ---------------- device scratch ----------------
__device__ float g_qpart[4*B_*U_];      // 4 D-split partials of query @ W1
__device__ float g_W2T[U_*D_];          // W2 transposed: [u][d]
__device__ float g_pscore[N_UT*B_*T_];  // per-uTile partial scores

// ---------------- helpers ----------------
__device__ __forceinline__ uint32_t f2tf32(float f){
    uint32_t r; asm("cvt.rna.tf32.f32 %0, %1;" : "=r"(r) : "f"(f)); return r;
}
__device__ __forceinline__ float tanh_fast(float x){
    float r; asm("tanh.approx.f32 %0, %1;" : "=f"(r) : "f"(x)); return r;
}
__device__ __forceinline__ void cp16(uint32_t smem, const void* gmem){
    asm volatile("cp.async.cg.shared.global [%0], [%1], 16;\n" :: "r"(smem), "l"(gmem));
}
__device__ __forceinline__ void mma_tf32(float c[4], const uint32_t a[4], const uint32_t b[2]){
    asm volatile(
        "mma.sync.aligned.m16n8k8.row.col.f32.tf32.tf32.f32 "
        "{%0,%1,%2,%3}, {%4,%5,%6,%7}, {%8,%9}, {%0,%1,%2,%3};\n"
        : "+f"(c[0]), "+f"(c[1]), "+f"(c[2]), "+f"(c[3])
        : "r"(a[0]), "r"(a[1]), "r"(a[2]), "r"(a[3]),
          "r"(b[0]), "r"(b[1]));
}

// ---------------- kernel 1: qproj partials over D-slices ----------------
__global__ __launch_bounds__(512) void qproj_kernel(
    const float* __restrict__ query, const float* __restrict__ W1)
{
    const int b = blockIdx.x, sp = blockIdx.y, tid = threadIdx.x;
    __shared__ float sq[128];
    if (tid < 128) sq[tid] = query[b*D_ + sp*128 + tid];
    __syncthreads();
    const float* w = W1 + (size_t)(sp*128)*U_ + tid;
    float acc = 0.f;
    #pragma unroll 8
    for (int d = 0; d < 128; d++)
        acc += sq[d] * w[(size_t)d*U_];
    g_qpart[(size_t)sp*(B_*U_) + b*U_ + tid] = acc;
}

// ---------------- kernel 1b: W2T[u][d] = W2[d][u]; zero context region ----------------
__global__ __launch_bounds__(256) void transpose_kernel(
    const float* __restrict__ W2, float* __restrict__ out)
{
    __shared__ float tile[32][33];
    const int bx = blockIdx.x*32, by = blockIdx.y*32;
    const int tx = threadIdx.x, ty = threadIdx.y;
    #pragma unroll
    for (int j = 0; j < 32; j += 8)
        tile[ty+j][tx] = W2[(size_t)(by+ty+j)*U_ + bx+tx];
    __syncthreads();
    #pragma unroll
    for (int j = 0; j < 32; j += 8)
        g_W2T[(size_t)(bx+ty+j)*D_ + by+tx] = tile[tx][ty+j];
    const int gid = (blockIdx.y*(U_/32) + blockIdx.x)*256 + ty*32 + tx;
    if (gid < CTX_OFF) out[gid] = 0.0f;
}

// ---------------- kernel 2: fused score GEMM (tf32 mma.sync) ----------------
// pscore[ut][b][t] = sum_{u in tile} Vw[u]*tanh(qp[b,u]+b2[u] + sum_d values[b,t,d]*W2[d,u])
__global__ __launch_bounds__(256, 2) void score_kernel(
    const float* __restrict__ values, const float* __restrict__ W1b,
    const float* __restrict__ W2b,    const float* __restrict__ Vw)
{
    extern __shared__ __align__(16) char smem[];
    float* sQP  = (float*)(smem + SM_QP);
    float* sVw  = (float*)(smem + SM_VW);
    float* ssum = (float*)(smem + SM_RED);

    const int tid = threadIdx.x;
    const int ut = blockIdx.x;
    const int t0 = blockIdx.y * BM;
    const int b  = blockIdx.z;
    const int u0 = ut * BN;
    const int warp = tid >> 5, lane = tid & 31;
    const int g = lane >> 2, tg = lane & 3;
    const int wm = warp >> 1, wn = warp & 1;     // 4 x 2 warps
    const int m0 = wm * 32,  n0 = wn * 64;

    if (tid < BN) {
        const int u = u0 + tid;
        sQP[tid] = g_qpart[u + b*U_] + g_qpart[B_*U_ + u + b*U_]
                 + g_qpart[2*B_*U_ + u + b*U_] + g_qpart[3*B_*U_ + u + b*U_]
                 + W1b[u] + W2b[u];
    } else {
        sVw[tid - BN] = Vw[u0 + tid - BN];
    }

    const float* Abase = values + ((size_t)b*T_ + t0) * D_;
    const float* Bbase = g_W2T + (size_t)u0 * D_;
    const uint32_t sA = (uint32_t)__cvta_generic_to_shared(smem + SM_A0);

    float c[2][8][4];
    #pragma unroll
    for (int mi = 0; mi < 2; mi++)
        #pragma unroll
        for (int ni = 0; ni < 8; ni++)
            #pragma unroll
            for (int q = 0; q < 4; q++) c[mi][ni][q] = 0.f;

    #define LOADC(KC, S) do {                                                   \
        const uint32_t as_ = sA + (S)*SM_STAGE;                                 \
        const uint32_t bs_ = as_ + SM_TILE;                                     \
        _Pragma("unroll")                                                       \
        for (int j = 0; j < 4; j++) {                                           \
            int idx = tid + j*256, r = idx >> 3, cc = idx & 7;                  \
            cp16(as_ + r*(LD*4) + cc*16, Abase + (size_t)r*D_ + (KC)*BK + cc*4);\
            cp16(bs_ + r*(LD*4) + cc*16, Bbase + (size_t)r*D_ + (KC)*BK + cc*4);\
        }                                                                       \
        asm volatile("cp.async.commit_group;\n");                               \
    } while (0)

    LOADC(0, 0);
    LOADC(1, 1);

    for (int kc = 0; kc < NKC; kc++) {
        if (kc < NKC-1) asm volatile("cp.async.wait_group 1;\n");
        else            asm volatile("cp.async.wait_group 0;\n");
        __syncthreads();
        const int s = kc & 1;
        const float* As = (const float*)(smem + SM_A0 + s*SM_STAGE);
        const float* Bs = (const float*)(smem + SM_A0 + s*SM_STAGE + SM_TILE);

        #pragma unroll
        for (int ks = 0; ks < BK; ks += 8) {
            uint32_t a[2][4], bb[8][2];
            #pragma unroll
            for (int mi = 0; mi < 2; mi++) {
                const float* ar = As + (m0 + mi*16 + g)*LD + ks + tg;
                a[mi][0] = __float_as_uint(ar[0]);
                a[mi][1] = __float_as_uint(ar[8*LD]);
                a[mi][2] = __float_as_uint(ar[4]);
                a[mi][3] = __float_as_uint(ar[8*LD + 4]);
            }
            #pragma unroll
            for (int ni = 0; ni < 8; ni++) {
                const float* br = Bs + (n0 + ni*8 + g)*LD + ks + tg;
                bb[ni][0] = __float_as_uint(br[0]);
                bb[ni][1] = __float_as_uint(br[4]);
            }
            #pragma unroll
            for (int mi = 0; mi < 2; mi++)
                #pragma unroll
                for (int q = 0; q < 4; q++)
                    a[mi][q] = f2tf32(__uint_as_float(a[mi][q]));
            #pragma unroll
            for (int ni = 0; ni < 8; ni++) {
                bb[ni][0] = f2tf32(__uint_as_float(bb[ni][0]));
                bb[ni][1] = f2tf32(__uint_as_float(bb[ni][1]));
            }
            #pragma unroll
            for (int mi = 0; mi < 2; mi++)
                #pragma unroll
                for (int ni = 0; ni < 8; ni++)
                    mma_tf32(c[mi][ni], a[mi], bb[ni]);
        }
        __syncthreads();
        if (kc + 2 < NKC) LOADC(kc + 2, s);
    }
    #undef LOADC

    // ---- epilogue: tanh + dot(Vw), reduce over u ----
    float rs[2][2] = {{0.f,0.f},{0.f,0.f}};
    #pragma unroll
    for (int mi = 0; mi < 2; mi++)
        #pragma unroll
        for (int ni = 0; ni < 8; ni++) {
            const int cN0 = n0 + ni*8 + 2*tg;
            #pragma unroll
            for (int h = 0; h < 2; h++)
                #pragma unroll
                for (int q = 0; q < 2; q++) {
                    float v = c[mi][ni][h*2 + q] + sQP[cN0 + q];
                    rs[mi][h] += tanh_fast(v) * sVw[cN0 + q];
                }
        }
    #pragma unroll
    for (int mi = 0; mi < 2; mi++)
        #pragma unroll
        for (int h = 0; h < 2; h++) {
            rs[mi][h] += __shfl_xor_sync(0xffffffffu, rs[mi][h], 1);
            rs[mi][h] += __shfl_xor_sync(0xffffffffu, rs[mi][h], 2);
        }
    if (tg == 0) {
        #pragma unroll
        for (int mi = 0; mi < 2; mi++)
            #pragma unroll
            for (int h = 0; h < 2; h++)
                ssum[wn*BM + m0 + mi*16 + h*8 + g] = rs[mi][h];
    }
    __syncthreads();
    if (tid < BM) {
        float s = ssum[tid] + ssum[BM + tid];
        g_pscore[(size_t)ut*(B_*T_) + b*T_ + t0 + tid] = s;
    }
}

// ---------------- kernel 3: softmax over T, write attn ----------------
__global__ __launch_bounds__(256) void softmax_kernel(
    const float* __restrict__ Vb, float* __restrict__ out)
{
    const int b = blockIdx.x, tid = threadIdx.x;
    __shared__ float red[256];
    float loc[8];
    const float vb = Vb[0];
    float mx = -1e30f;
    #pragma unroll
    for (int j = 0; j < 8; j++) {
        int t = tid + j*256;
        float s = vb;
        #pragma unroll
        for (int i = 0; i < N_UT; i++) s += g_pscore[i*(B_*T_) + b*T_ + t];
        loc[j] = s;
        mx = fmaxf(mx, s);
    }
    red[tid] = mx; __syncthreads();
    #pragma unroll
    for (int s = 128; s > 0; s >>= 1) {
        if (tid < s) red[tid] = fmaxf(red[tid], red[tid + s]);
        __syncthreads();
    }
    mx = red[0]; __syncthreads();
    float se = 0.f;
    #pragma unroll
    for (int j = 0; j < 8; j++) { loc[j] = __expf(loc[j] - mx); se += loc[j]; }
    red[tid] = se; __syncthreads();
    #pragma unroll
    for (int s = 128; s > 0; s >>= 1) {
        if (tid < s) red[tid] += red[tid + s];
        __syncthreads();
    }
    const float inv = 1.0f / red[0];
    #pragma unroll
    for (int j = 0; j < 8; j++)
        out[CTX_OFF + b*T_ + tid + j*256] = loc[j] * inv;
}

// ---------------- kernel 4: context = sum_t attn * values ----------------
__global__ __launch_bounds__(512) void context_kernel(
    const float* __restrict__ values, float* __restrict__ out)
{
    const int b = blockIdx.x, tid = threadIdx.x;
    const int t0 = blockIdx.y * 256;
    const int tl = tid >> 7;          // t-lane 0..3
    const int dt = tid & 127;         // d-group
    __shared__ float sa[256];
    __shared__ float4 sred[512];
    if (tid < 256) sa[tid] = out[CTX_OFF + b*T_ + t0 + tid];
    __syncthreads();
    const float* vp = values + ((size_t)b*T_ + t0)*D_ + dt*4;
    float4 acc = {0.f, 0.f, 0.f, 0.f};
    #pragma unroll 4
    for (int tt = tl; tt < 256; tt += 4) {
        const float4 v = *(const float4*)(vp + (size_t)tt*D_);
        const float w = sa[tt];
        acc.x += w*v.x; acc.y += w*v.y; acc.z += w*v.z; acc.w += w*v.w;
    }
    sred[tid] = acc;
    __syncthreads();
    if (tid < 128) {
        float4 r0 = sred[tid], r1 = sred[tid+128], r2 = sred[tid+256], r3 = sred[tid+384];
        atomicAdd(&out[b*D_ + tid*4    ], r0.x + r1.x + r2.x + r3.x);
        atomicAdd(&out[b*D_ + tid*4 + 1], r0.y + r1.y + r2.y + r3.y);
        atomicAdd(&out[b*D_ + tid*4 + 2], r0.z + r1.z + r2.z + r3.z);
        atomicAdd(&out[b*D_ + tid*4 + 3], r0.w + r1.w + r2.w + r3.w);
    }
}

// ---------------- launch ----------------
extern "C" void kernel_launch(void* const* d_in, const int* in_sizes, int n_in,
                              void* d_out, int out_size)
{
    const float* query  = (const float*)d_in[0];
    const float* values = (const float*)d_in[1];
    const float* W1w    = (const float*)d_in[2];
    const float* W1b    = (const float*)d_in[3];
    const float* W2w    = (const float*)d_in[4];
    const float* W2b    = (const float*)d_in[5];
    const float* Vw     = (const float*)d_in[6];
    const float* Vb     = (const float*)d_in[7];
    float* out = (float*)d_out;

    cudaFuncSetAttribute(score_kernel, cudaFuncAttributeMaxDynamicSharedMemorySize, SM_TOTAL);

    qproj_kernel<<<dim3(B_, 4), 512>>>(query, W1w);
    transpose_kernel<<<dim3(U_/32, D_/32), dim3(32, 8)>>>(W2w, out);
    score_kernel<<<dim3(N_UT, T_/BM, B_), 256, SM_TOTAL>>>(values, W1b, W2b, Vw);
    softmax_kernel<<<B_, 256>>>(Vb, out);
    context_kernel<<<dim3(B_, T_/256), 512>>>(values, out);
}

// round 7
// speedup vs baseline: 1.9311x; 1.5527x over previous
#include <cuda_runtime.h>
#include <cuda_fp16.h>
#include <cstdint>
#include <cstddef>

#define B_ 32
#define T_ 2048
#define D_ 512
#define U_ 512
#define CTX_OFF (B_*D_)   // context at [0:16384], attn at [16384:]

// score-GEMM tiling: fp16 mma.sync m16n8k16
#define BM 128
#define BN 128
#define BK 64
#define NKC (D_/BK)       // 8 chunks
#define N_UT (U_/BN)      // 4 u-tiles
#define LDH 72            // padded row stride in halfs (144B) — conflict-free frags

// dynamic smem for score kernel
#define SM_QP    0                      // 128 floats
#define SM_VW    512                    // 128 floats
#define SM_RED   1024                   // ssum[2][128] floats
#define SM_A0    2048
#define SM_TILE  (BM*LDH*2)             // 18432 B (A or B)
#define SM_STAGE (2*SM_TILE)            // 36864 B
#define SM_TOTAL (SM_A0 + 2*SM_STAGE)   // 75776 B -> 2 CTAs/SM

// ---------------- device scratch ----------------
__device__ __half g_vhalf[(size_t)B_*T_*D_];   // fp16 copy of values (67 MB)
__device__ __half g_W2Th[U_*D_];               // W2^T in fp16: [u][d]
__device__ float  g_qpart[4*B_*U_];
__device__ float  g_pscore[N_UT*B_*T_];

// ---------------- helpers ----------------
__device__ __forceinline__ uint32_t h2_as_u32(__half2 h){
    uint32_t u; __builtin_memcpy(&u, &h, 4); return u;
}
__device__ __forceinline__ float tanh_fast(float x){
    float r; asm("tanh.approx.f32 %0, %1;" : "=f"(r) : "f"(x)); return r;
}
__device__ __forceinline__ void cp16(uint32_t smem, const void* gmem){
    asm volatile("cp.async.cg.shared.global [%0], [%1], 16;\n" :: "r"(smem), "l"(gmem));
}
__device__ __forceinline__ void mma_f16(float c[4], const uint32_t a[4], const uint32_t b[2]){
    asm volatile(
        "mma.sync.aligned.m16n8k16.row.col.f32.f16.f16.f32 "
        "{%0,%1,%2,%3}, {%4,%5,%6,%7}, {%8,%9}, {%0,%1,%2,%3};\n"
        : "+f"(c[0]), "+f"(c[1]), "+f"(c[2]), "+f"(c[3])
        : "r"(a[0]), "r"(a[1]), "r"(a[2]), "r"(a[3]),
          "r"(b[0]), "r"(b[1]));
}

// ---------------- kernel 0: values fp32 -> fp16 ----------------
__global__ __launch_bounds__(256) void convert_kernel(const float4* __restrict__ v)
{
    const size_t i = (size_t)blockIdx.x*256 + threadIdx.x;   // 8 floats each
    const float4 f0 = v[2*i], f1 = v[2*i+1];
    uint4 o;
    o.x = h2_as_u32(__floats2half2_rn(f0.x, f0.y));
    o.y = h2_as_u32(__floats2half2_rn(f0.z, f0.w));
    o.z = h2_as_u32(__floats2half2_rn(f1.x, f1.y));
    o.w = h2_as_u32(__floats2half2_rn(f1.z, f1.w));
    ((uint4*)g_vhalf)[i] = o;
}

// ---------------- kernel 1: qproj partials over D-slices ----------------
__global__ __launch_bounds__(512) void qproj_kernel(
    const float* __restrict__ query, const float* __restrict__ W1)
{
    const int b = blockIdx.x, sp = blockIdx.y, tid = threadIdx.x;
    __shared__ float sq[128];
    if (tid < 128) sq[tid] = query[b*D_ + sp*128 + tid];
    __syncthreads();
    const float* w = W1 + (size_t)(sp*128)*U_ + tid;
    float acc = 0.f;
    #pragma unroll 8
    for (int d = 0; d < 128; d++)
        acc += sq[d] * w[(size_t)d*U_];
    g_qpart[(size_t)sp*(B_*U_) + b*U_ + tid] = acc;
}

// ---------------- kernel 1b: W2Th[u][d] = half(W2[d][u]); zero context ----------------
__global__ __launch_bounds__(256) void transpose_kernel(
    const float* __restrict__ W2, float* __restrict__ out)
{
    __shared__ float tile[32][33];
    const int bx = blockIdx.x*32, by = blockIdx.y*32;
    const int tx = threadIdx.x, ty = threadIdx.y;
    #pragma unroll
    for (int j = 0; j < 32; j += 8)
        tile[ty+j][tx] = W2[(size_t)(by+ty+j)*U_ + bx+tx];
    __syncthreads();
    #pragma unroll
    for (int j = 0; j < 32; j += 8)
        g_W2Th[(size_t)(bx+ty+j)*D_ + by+tx] = __float2half_rn(tile[tx][ty+j]);
    const int gid = (blockIdx.y*(U_/32) + blockIdx.x)*256 + ty*32 + tx;
    if (gid < CTX_OFF) out[gid] = 0.0f;
}

// ---------------- kernel 2: fused score GEMM (fp16 mma.sync m16n8k16) ----------------
__global__ __launch_bounds__(256, 2) void score_kernel(
    const float* __restrict__ W1b, const float* __restrict__ W2b,
    const float* __restrict__ Vw)
{
    extern __shared__ __align__(16) char smem[];
    float* sQP  = (float*)(smem + SM_QP);
    float* sVw  = (float*)(smem + SM_VW);
    float* ssum = (float*)(smem + SM_RED);

    const int tid = threadIdx.x;
    const int ut = blockIdx.x;
    const int t0 = blockIdx.y * BM;
    const int b  = blockIdx.z;
    const int u0 = ut * BN;
    const int warp = tid >> 5, lane = tid & 31;
    const int g = lane >> 2, tg = lane & 3;
    const int wm = warp >> 1, wn = warp & 1;     // 4 x 2 warps
    const int m0 = wm * 32,  n0 = wn * 64;

    if (tid < BN) {
        const int u = u0 + tid;
        sQP[tid] = g_qpart[u + b*U_] + g_qpart[B_*U_ + u + b*U_]
                 + g_qpart[2*B_*U_ + u + b*U_] + g_qpart[3*B_*U_ + u + b*U_]
                 + W1b[u] + W2b[u];
    } else {
        sVw[tid - BN] = Vw[u0 + tid - BN];
    }

    const __half* Abase = g_vhalf + ((size_t)b*T_ + t0) * D_;
    const __half* Bbase = g_W2Th + (size_t)u0 * D_;
    const uint32_t sA = (uint32_t)__cvta_generic_to_shared(smem + SM_A0);

    float c[2][8][4];
    #pragma unroll
    for (int mi = 0; mi < 2; mi++)
        #pragma unroll
        for (int ni = 0; ni < 8; ni++)
            #pragma unroll
            for (int q = 0; q < 4; q++) c[mi][ni][q] = 0.f;

    // per stage: A 128 rows x 64 halfs (8 cp16/row), B same
    #define LOADC(KC, S) do {                                                   \
        const uint32_t as_ = sA + (S)*SM_STAGE;                                 \
        const uint32_t bs_ = as_ + SM_TILE;                                     \
        _Pragma("unroll")                                                       \
        for (int j = 0; j < 4; j++) {                                           \
            int idx = tid + j*256, r = idx >> 3, cc = idx & 7;                  \
            cp16(as_ + r*(LDH*2) + cc*16, Abase + (size_t)r*D_ + (KC)*BK + cc*8);\
            cp16(bs_ + r*(LDH*2) + cc*16, Bbase + (size_t)r*D_ + (KC)*BK + cc*8);\
        }                                                                       \
        asm volatile("cp.async.commit_group;\n");                               \
    } while (0)

    LOADC(0, 0);
    LOADC(1, 1);

    for (int kc = 0; kc < NKC; kc++) {
        if (kc < NKC-1) asm volatile("cp.async.wait_group 1;\n");
        else            asm volatile("cp.async.wait_group 0;\n");
        __syncthreads();
        const int s = kc & 1;
        const __half* As = (const __half*)(smem + SM_A0 + s*SM_STAGE);
        const __half* Bs = (const __half*)(smem + SM_A0 + s*SM_STAGE + SM_TILE);

        #pragma unroll
        for (int ks = 0; ks < BK; ks += 16) {
            uint32_t a[2][4], bb[8][2];
            #pragma unroll
            for (int mi = 0; mi < 2; mi++) {
                const __half* ar = As + (m0 + mi*16 + g)*LDH + ks + 2*tg;
                a[mi][0] = *(const uint32_t*)(ar);
                a[mi][1] = *(const uint32_t*)(ar + 8*LDH);
                a[mi][2] = *(const uint32_t*)(ar + 8);
                a[mi][3] = *(const uint32_t*)(ar + 8*LDH + 8);
            }
            #pragma unroll
            for (int ni = 0; ni < 8; ni++) {
                const __half* br = Bs + (n0 + ni*8 + g)*LDH + ks + 2*tg;
                bb[ni][0] = *(const uint32_t*)(br);
                bb[ni][1] = *(const uint32_t*)(br + 8);
            }
            #pragma unroll
            for (int mi = 0; mi < 2; mi++)
                #pragma unroll
                for (int ni = 0; ni < 8; ni++)
                    mma_f16(c[mi][ni], a[mi], bb[ni]);
        }
        __syncthreads();
        if (kc + 2 < NKC) LOADC(kc + 2, s);
    }
    #undef LOADC

    // ---- epilogue: tanh + dot(Vw), reduce over u ----
    float rs[2][2] = {{0.f,0.f},{0.f,0.f}};
    #pragma unroll
    for (int mi = 0; mi < 2; mi++)
        #pragma unroll
        for (int ni = 0; ni < 8; ni++) {
            const int cN0 = n0 + ni*8 + 2*tg;
            #pragma unroll
            for (int h = 0; h < 2; h++)
                #pragma unroll
                for (int q = 0; q < 2; q++) {
                    float v = c[mi][ni][h*2 + q] + sQP[cN0 + q];
                    rs[mi][h] += tanh_fast(v) * sVw[cN0 + q];
                }
        }
    #pragma unroll
    for (int mi = 0; mi < 2; mi++)
        #pragma unroll
        for (int h = 0; h < 2; h++) {
            rs[mi][h] += __shfl_xor_sync(0xffffffffu, rs[mi][h], 1);
            rs[mi][h] += __shfl_xor_sync(0xffffffffu, rs[mi][h], 2);
        }
    if (tg == 0) {
        #pragma unroll
        for (int mi = 0; mi < 2; mi++)
            #pragma unroll
            for (int h = 0; h < 2; h++)
                ssum[wn*BM + m0 + mi*16 + h*8 + g] = rs[mi][h];
    }
    __syncthreads();
    if (tid < BM) {
        float s = ssum[tid] + ssum[BM + tid];
        g_pscore[(size_t)ut*(B_*T_) + b*T_ + t0 + tid] = s;
    }
}

// ---------------- kernel 3: softmax over T, write attn ----------------
__global__ __launch_bounds__(512) void softmax_kernel(
    const float* __restrict__ Vb, float* __restrict__ out)
{
    const int b = blockIdx.x, tid = threadIdx.x;
    __shared__ float red[512];
    float loc[4];
    const float vb = Vb[0];
    float mx = -1e30f;
    #pragma unroll
    for (int j = 0; j < 4; j++) {
        int t = tid + j*512;
        float s = vb;
        #pragma unroll
        for (int i = 0; i < N_UT; i++) s += g_pscore[i*(B_*T_) + b*T_ + t];
        loc[j] = s;
        mx = fmaxf(mx, s);
    }
    red[tid] = mx; __syncthreads();
    #pragma unroll
    for (int s = 256; s > 0; s >>= 1) {
        if (tid < s) red[tid] = fmaxf(red[tid], red[tid + s]);
        __syncthreads();
    }
    mx = red[0]; __syncthreads();
    float se = 0.f;
    #pragma unroll
    for (int j = 0; j < 4; j++) { loc[j] = __expf(loc[j] - mx); se += loc[j]; }
    red[tid] = se; __syncthreads();
    #pragma unroll
    for (int s = 256; s > 0; s >>= 1) {
        if (tid < s) red[tid] += red[tid + s];
        __syncthreads();
    }
    const float inv = 1.0f / red[0];
    #pragma unroll
    for (int j = 0; j < 4; j++)
        out[CTX_OFF + b*T_ + tid + j*512] = loc[j] * inv;
}

// ---------------- kernel 4: context = sum_t attn * values (fp16 values) ----------------
__global__ __launch_bounds__(512) void context_kernel(float* __restrict__ out)
{
    const int b = blockIdx.x, tid = threadIdx.x;
    const int t0 = blockIdx.y * 256;
    const int tl = tid >> 6;          // t-lane 0..7
    const int dt = tid & 63;          // d-group: 8 halfs each
    __shared__ float sa[256];
    __shared__ float4 sredA[512];
    __shared__ float4 sredB[512];
    if (tid < 256) sa[tid] = out[CTX_OFF + b*T_ + t0 + tid];
    __syncthreads();
    const uint4* vp = (const uint4*)(g_vhalf + ((size_t)b*T_ + t0)*D_) + dt;
    float4 aA = {0.f,0.f,0.f,0.f}, aB = {0.f,0.f,0.f,0.f};
    #pragma unroll 4
    for (int tt = tl; tt < 256; tt += 8) {
        const uint4 u = vp[(size_t)tt*(D_/8)];
        const float w = sa[tt];
        const float2 f0 = __half22float2(*(const __half2*)&u.x);
        const float2 f1 = __half22float2(*(const __half2*)&u.y);
        const float2 f2 = __half22float2(*(const __half2*)&u.z);
        const float2 f3 = __half22float2(*(const __half2*)&u.w);
        aA.x += w*f0.x; aA.y += w*f0.y; aA.z += w*f1.x; aA.w += w*f1.y;
        aB.x += w*f2.x; aB.y += w*f2.y; aB.z += w*f3.x; aB.w += w*f3.y;
    }
    sredA[tid] = aA; sredB[tid] = aB;
    __syncthreads();
    if (tid < 64) {
        float4 rA = sredA[tid], rB = sredB[tid];
        #pragma unroll
        for (int l = 1; l < 8; l++) {
            const float4 qA = sredA[l*64 + tid], qB = sredB[l*64 + tid];
            rA.x += qA.x; rA.y += qA.y; rA.z += qA.z; rA.w += qA.w;
            rB.x += qB.x; rB.y += qB.y; rB.z += qB.z; rB.w += qB.w;
        }
        float* o = out + b*D_ + tid*8;
        atomicAdd(o+0, rA.x); atomicAdd(o+1, rA.y);
        atomicAdd(o+2, rA.z); atomicAdd(o+3, rA.w);
        atomicAdd(o+4, rB.x); atomicAdd(o+5, rB.y);
        atomicAdd(o+6, rB.z); atomicAdd(o+7, rB.w);
    }
}

// ---------------- launch ----------------
extern "C" void kernel_launch(void* const* d_in, const int* in_sizes, int n_in,
                              void* d_out, int out_size)
{
    const float* query  = (const float*)d_in[0];
    const float* values = (const float*)d_in[1];
    const float* W1w    = (const float*)d_in[2];
    const float* W1b    = (const float*)d_in[3];
    const float* W2w    = (const float*)d_in[4];
    const float* W2b    = (const float*)d_in[5];
    const float* Vw     = (const float*)d_in[6];
    const float* Vb     = (const float*)d_in[7];
    float* out = (float*)d_out;

    cudaFuncSetAttribute(score_kernel, cudaFuncAttributeMaxDynamicSharedMemorySize, SM_TOTAL);

    convert_kernel<<<(B_*T_*D_)/(256*8), 256>>>((const float4*)values);
    qproj_kernel<<<dim3(B_, 4), 512>>>(query, W1w);
    transpose_kernel<<<dim3(U_/32, D_/32), dim3(32, 8)>>>(W2w, out);
    score_kernel<<<dim3(N_UT, T_/BM, B_), 256, SM_TOTAL>>>(W1b, W2b, Vw);
    softmax_kernel<<<B_, 512>>>(Vb, out);
    context_kernel<<<dim3(B_, T_/256), 512>>>(out);
}

// round 11
// speedup vs baseline: 1.9983x; 1.0348x over previous
#include <cuda_runtime.h>
#include <cuda_fp16.h>
#include <cstdint>
#include <cstddef>

#define B_ 32
#define T_ 2048
#define D_ 512
#define U_ 512
#define CTX_OFF (B_*D_)   // context at [0:16384], attn at [16384:]

// score-GEMM tiling: fp16 mma.sync m16n8k16, 512 threads, warp tile 32x32
#define BM 128
#define BN 128
#define BK 64
#define NKC (D_/BK)       // 8 chunks
#define N_UT (U_/BN)      // 4 u-tiles
#define LDH 72            // padded row stride in halfs (144B) — ldmatrix conflict-free

// dynamic smem for score kernel
#define SM_QP    0                      // 128 floats
#define SM_VW    512                    // 128 floats
#define SM_RED   1024                   // ssum[4][128] floats = 2048B
#define SM_A0    4096
#define SM_TILE  (BM*LDH*2)             // 18432 B (A or B)
#define SM_STAGE (2*SM_TILE)            // 36864 B
#define SM_TOTAL (SM_A0 + 2*SM_STAGE)   // 77824 B

// ---------------- device scratch ----------------
__device__ __half g_vhalf[(size_t)B_*T_*D_];   // fp16 copy of values (67 MB)
__device__ __half g_W2Th[U_*D_];               // W2^T in fp16: [u][d]
__device__ float  g_qpart[4*B_*U_];
__device__ float  g_pscore[N_UT*B_*T_];

// ---------------- helpers ----------------
__device__ __forceinline__ uint32_t h2_as_u32(__half2 h){
    uint32_t u; __builtin_memcpy(&u, &h, 4); return u;
}
__device__ __forceinline__ float tanh_fast(float x){
    float r; asm("tanh.approx.f32 %0, %1;" : "=f"(r) : "f"(x)); return r;
}
__device__ __forceinline__ void cp16(uint32_t smem, const void* gmem){
    asm volatile("cp.async.cg.shared.global [%0], [%1], 16;\n" :: "r"(smem), "l"(gmem));
}
__device__ __forceinline__ void ldm_x4(uint32_t r[4], uint32_t addr){
    asm volatile("ldmatrix.sync.aligned.m8n8.x4.shared.b16 {%0,%1,%2,%3}, [%4];"
        : "=r"(r[0]), "=r"(r[1]), "=r"(r[2]), "=r"(r[3]) : "r"(addr));
}
__device__ __forceinline__ void mma_f16(float c[4], const uint32_t a[4],
                                        uint32_t b0, uint32_t b1){
    asm volatile(
        "mma.sync.aligned.m16n8k16.row.col.f32.f16.f16.f32 "
        "{%0,%1,%2,%3}, {%4,%5,%6,%7}, {%8,%9}, {%0,%1,%2,%3};\n"
        : "+f"(c[0]), "+f"(c[1]), "+f"(c[2]), "+f"(c[3])
        : "r"(a[0]), "r"(a[1]), "r"(a[2]), "r"(a[3]),
          "r"(b0), "r"(b1));
}

// ---------------- kernel 0: values fp32 -> fp16 ----------------
__global__ __launch_bounds__(256) void convert_kernel(const float4* __restrict__ v)
{
    const size_t i = (size_t)blockIdx.x*256 + threadIdx.x;   // 8 floats each
    const float4 f0 = v[2*i], f1 = v[2*i+1];
    uint4 o;
    o.x = h2_as_u32(__floats2half2_rn(f0.x, f0.y));
    o.y = h2_as_u32(__floats2half2_rn(f0.z, f0.w));
    o.z = h2_as_u32(__floats2half2_rn(f1.x, f1.y));
    o.w = h2_as_u32(__floats2half2_rn(f1.z, f1.w));
    ((uint4*)g_vhalf)[i] = o;
}

// ---------------- kernel 1: qproj partials over D-slices ----------------
__global__ __launch_bounds__(512) void qproj_kernel(
    const float* __restrict__ query, const float* __restrict__ W1)
{
    const int b = blockIdx.x, sp = blockIdx.y, tid = threadIdx.x;
    __shared__ float sq[128];
    if (tid < 128) sq[tid] = query[b*D_ + sp*128 + tid];
    __syncthreads();
    const float* w = W1 + (size_t)(sp*128)*U_ + tid;
    float acc = 0.f;
    #pragma unroll 8
    for (int d = 0; d < 128; d++)
        acc += sq[d] * w[(size_t)d*U_];
    g_qpart[(size_t)sp*(B_*U_) + b*U_ + tid] = acc;
}

// ---------------- kernel 1b: W2Th[u][d] = half(W2[d][u]); zero context ----------------
__global__ __launch_bounds__(256) void transpose_kernel(
    const float* __restrict__ W2, float* __restrict__ out)
{
    __shared__ float tile[32][33];
    const int bx = blockIdx.x*32, by = blockIdx.y*32;
    const int tx = threadIdx.x, ty = threadIdx.y;
    #pragma unroll
    for (int j = 0; j < 32; j += 8)
        tile[ty+j][tx] = W2[(size_t)(by+ty+j)*U_ + bx+tx];
    __syncthreads();
    #pragma unroll
    for (int j = 0; j < 32; j += 8)
        g_W2Th[(size_t)(bx+ty+j)*D_ + by+tx] = __float2half_rn(tile[tx][ty+j]);
    const int gid = (blockIdx.y*(U_/32) + blockIdx.x)*256 + ty*32 + tx;
    if (gid < CTX_OFF) out[gid] = 0.0f;
}

// ---------------- kernel 2: fused score GEMM (fp16 mma + ldmatrix) ----------------
__global__ __launch_bounds__(512, 2) void score_kernel(
    const float* __restrict__ W1b, const float* __restrict__ W2b,
    const float* __restrict__ Vw)
{
    extern __shared__ __align__(1024) char smem[];
    float* sQP  = (float*)(smem + SM_QP);
    float* sVw  = (float*)(smem + SM_VW);
    float* ssum = (float*)(smem + SM_RED);

    const int tid = threadIdx.x;
    const int ut = blockIdx.x;
    const int t0 = blockIdx.y * BM;
    const int b  = blockIdx.z;
    const int u0 = ut * BN;
    const int warp = tid >> 5, lane = tid & 31;
    const int g = lane >> 2, tg = lane & 3;
    const int wm = warp >> 2, wn = warp & 3;     // 4 x 4 warps
    const int m0 = wm * 32,  n0 = wn * 32;

    if (tid < BN) {
        const int u = u0 + tid;
        sQP[tid] = g_qpart[u + b*U_] + g_qpart[B_*U_ + u + b*U_]
                 + g_qpart[2*B_*U_ + u + b*U_] + g_qpart[3*B_*U_ + u + b*U_]
                 + W1b[u] + W2b[u];
    } else if (tid < 2*BN) {
        sVw[tid - BN] = Vw[u0 + tid - BN];
    }

    const __half* Abase = g_vhalf + ((size_t)b*T_ + t0) * D_;
    const __half* Bbase = g_W2Th + (size_t)u0 * D_;
    const uint32_t sA = (uint32_t)__cvta_generic_to_shared(smem + SM_A0);

    // ldmatrix per-lane addresses (byte offsets within tile)
    const int arow = m0 + (lane & 15);
    const int acol = (lane & 16) ? 8 : 0;
    const int brow = n0 + (lane & 7) + ((lane & 16) >> 1);
    const int bcol = lane & 8;
    const uint32_t aoff = (uint32_t)(arow*LDH + acol) * 2;
    const uint32_t boff = (uint32_t)(brow*LDH + bcol) * 2;

    float c[2][4][4];
    #pragma unroll
    for (int mi = 0; mi < 2; mi++)
        #pragma unroll
        for (int ni = 0; ni < 4; ni++)
            #pragma unroll
            for (int q = 0; q < 4; q++) c[mi][ni][q] = 0.f;

    // per stage: A 128 rows x 64 halfs (8 cp16/row) + B same; 512 threads x 2 iters
    #define LOADC(KC, S) do {                                                    \
        const uint32_t as_ = sA + (S)*SM_STAGE;                                  \
        const uint32_t bs_ = as_ + SM_TILE;                                      \
        _Pragma("unroll")                                                        \
        for (int j = 0; j < 2; j++) {                                            \
            int idx = tid + j*512, r = idx >> 3, cc = idx & 7;                   \
            cp16(as_ + r*(LDH*2) + cc*16, Abase + (size_t)r*D_ + (KC)*BK + cc*8);\
            cp16(bs_ + r*(LDH*2) + cc*16, Bbase + (size_t)r*D_ + (KC)*BK + cc*8);\
        }                                                                        \
        asm volatile("cp.async.commit_group;\n");                                \
    } while (0)

    LOADC(0, 0);
    LOADC(1, 1);

    for (int kc = 0; kc < NKC; kc++) {
        if (kc < NKC-1) asm volatile("cp.async.wait_group 1;\n");
        else            asm volatile("cp.async.wait_group 0;\n");
        __syncthreads();
        const int s = kc & 1;
        const uint32_t aAddr = sA + s*SM_STAGE + aoff;
        const uint32_t bAddr = sA + s*SM_STAGE + SM_TILE + boff;

        #pragma unroll
        for (int ks = 0; ks < BK; ks += 16) {
            uint32_t a[2][4], bb[2][4];
            ldm_x4(a[0],  aAddr + ks*2);
            ldm_x4(a[1],  aAddr + 16*LDH*2 + ks*2);
            ldm_x4(bb[0], bAddr + ks*2);
            ldm_x4(bb[1], bAddr + 16*LDH*2 + ks*2);
            #pragma unroll
            for (int mi = 0; mi < 2; mi++)
                #pragma unroll
                for (int ni = 0; ni < 4; ni++)
                    mma_f16(c[mi][ni], a[mi],
                            bb[ni>>1][2*(ni&1)], bb[ni>>1][2*(ni&1)+1]);
        }
        __syncthreads();
        if (kc + 2 < NKC) LOADC(kc + 2, s);
    }
    #undef LOADC

    // ---- epilogue: tanh + dot(Vw), reduce over u ----
    float rs[2][2] = {{0.f,0.f},{0.f,0.f}};
    #pragma unroll
    for (int mi = 0; mi < 2; mi++)
        #pragma unroll
        for (int ni = 0; ni < 4; ni++) {
            const int cN0 = n0 + ni*8 + 2*tg;
            #pragma unroll
            for (int h = 0; h < 2; h++)
                #pragma unroll
                for (int q = 0; q < 2; q++) {
                    float v = c[mi][ni][h*2 + q] + sQP[cN0 + q];
                    rs[mi][h] += tanh_fast(v) * sVw[cN0 + q];
                }
        }
    #pragma unroll
    for (int mi = 0; mi < 2; mi++)
        #pragma unroll
        for (int h = 0; h < 2; h++) {
            rs[mi][h] += __shfl_xor_sync(0xffffffffu, rs[mi][h], 1);
            rs[mi][h] += __shfl_xor_sync(0xffffffffu, rs[mi][h], 2);
        }
    if (tg == 0) {
        #pragma unroll
        for (int mi = 0; mi < 2; mi++)
            #pragma unroll
            for (int h = 0; h < 2; h++)
                ssum[wn*BM + m0 + mi*16 + h*8 + g] = rs[mi][h];
    }
    __syncthreads();
    if (tid < BM) {
        float s = ssum[tid] + ssum[BM + tid] + ssum[2*BM + tid] + ssum[3*BM + tid];
        g_pscore[(size_t)ut*(B_*T_) + b*T_ + t0 + tid] = s;
    }
}

// ---------------- kernel 3: softmax over T, write attn ----------------
__global__ __launch_bounds__(512) void softmax_kernel(
    const float* __restrict__ Vb, float* __restrict__ out)
{
    const int b = blockIdx.x, tid = threadIdx.x;
    __shared__ float red[512];
    float loc[4];
    const float vb = Vb[0];
    float mx = -1e30f;
    #pragma unroll
    for (int j = 0; j < 4; j++) {
        int t = tid + j*512;
        float s = vb;
        #pragma unroll
        for (int i = 0; i < N_UT; i++) s += g_pscore[i*(B_*T_) + b*T_ + t];
        loc[j] = s;
        mx = fmaxf(mx, s);
    }
    red[tid] = mx; __syncthreads();
    #pragma unroll
    for (int s = 256; s > 0; s >>= 1) {
        if (tid < s) red[tid] = fmaxf(red[tid], red[tid + s]);
        __syncthreads();
    }
    mx = red[0]; __syncthreads();
    float se = 0.f;
    #pragma unroll
    for (int j = 0; j < 4; j++) { loc[j] = __expf(loc[j] - mx); se += loc[j]; }
    red[tid] = se; __syncthreads();
    #pragma unroll
    for (int s = 256; s > 0; s >>= 1) {
        if (tid < s) red[tid] += red[tid + s];
        __syncthreads();
    }
    const float inv = 1.0f / red[0];
    #pragma unroll
    for (int j = 0; j < 4; j++)
        out[CTX_OFF + b*T_ + tid + j*512] = loc[j] * inv;
}

// ---------------- kernel 4: context = sum_t attn * values (fp16 values) ----------------
__global__ __launch_bounds__(512) void context_kernel(float* __restrict__ out)
{
    const int b = blockIdx.x, tid = threadIdx.x;
    const int t0 = blockIdx.y * 256;
    const int tl = tid >> 6;          // t-lane 0..7
    const int dt = tid & 63;          // d-group: 8 halfs each
    __shared__ float sa[256];
    __shared__ float4 sredA[512];
    __shared__ float4 sredB[512];
    if (tid < 256) sa[tid] = out[CTX_OFF + b*T_ + t0 + tid];
    __syncthreads();
    const uint4* vp = (const uint4*)(g_vhalf + ((size_t)b*T_ + t0)*D_) + dt;
    float4 aA = {0.f,0.f,0.f,0.f}, aB = {0.f,0.f,0.f,0.f};
    #pragma unroll 4
    for (int tt = tl; tt < 256; tt += 8) {
        const uint4 u = vp[(size_t)tt*(D_/8)];
        const float w = sa[tt];
        const float2 f0 = __half22float2(*(const __half2*)&u.x);
        const float2 f1 = __half22float2(*(const __half2*)&u.y);
        const float2 f2 = __half22float2(*(const __half2*)&u.z);
        const float2 f3 = __half22float2(*(const __half2*)&u.w);
        aA.x += w*f0.x; aA.y += w*f0.y; aA.z += w*f1.x; aA.w += w*f1.y;
        aB.x += w*f2.x; aB.y += w*f2.y; aB.z += w*f3.x; aB.w += w*f3.y;
    }
    sredA[tid] = aA; sredB[tid] = aB;
    __syncthreads();
    if (tid < 64) {
        float4 rA = sredA[tid], rB = sredB[tid];
        #pragma unroll
        for (int l = 1; l < 8; l++) {
            const float4 qA = sredA[l*64 + tid], qB = sredB[l*64 + tid];
            rA.x += qA.x; rA.y += qA.y; rA.z += qA.z; rA.w += qA.w;
            rB.x += qB.x; rB.y += qB.y; rB.z += qB.z; rB.w += qB.w;
        }
        float* o = out + b*D_ + tid*8;
        atomicAdd(o+0, rA.x); atomicAdd(o+1, rA.y);
        atomicAdd(o+2, rA.z); atomicAdd(o+3, rA.w);
        atomicAdd(o+4, rB.x); atomicAdd(o+5, rB.y);
        atomicAdd(o+6, rB.z); atomicAdd(o+7, rB.w);
    }
}

// ---------------- launch ----------------
extern "C" void kernel_launch(void* const* d_in, const int* in_sizes, int n_in,
                              void* d_out, int out_size)
{
    const float* query  = (const float*)d_in[0];
    const float* values = (const float*)d_in[1];
    const float* W1w    = (const float*)d_in[2];
    const float* W1b    = (const float*)d_in[3];
    const float* W2w    = (const float*)d_in[4];
    const float* W2b    = (const float*)d_in[5];
    const float* Vw     = (const float*)d_in[6];
    const float* Vb     = (const float*)d_in[7];
    float* out = (float*)d_out;

    cudaFuncSetAttribute(score_kernel, cudaFuncAttributeMaxDynamicSharedMemorySize, SM_TOTAL);

    convert_kernel<<<(B_*T_*D_)/(256*8), 256>>>((const float4*)values);
    qproj_kernel<<<dim3(B_, 4), 512>>>(query, W1w);
    transpose_kernel<<<dim3(U_/32, D_/32), dim3(32, 8)>>>(W2w, out);
    score_kernel<<<dim3(N_UT, T_/BM, B_), 512, SM_TOTAL>>>(W1b, W2b, Vw);
    softmax_kernel<<<B_, 512>>>(Vb, out);
    context_kernel<<<dim3(B_, T_/256), 512>>>(out);
}